// round 15
// baseline (speedup 1.0000x reference)
#include <cuda_runtime.h>
#include <cuda_fp16.h>
#include <stdint.h>

#define NBATCH 16
#define SEQL   100
#define DIM    512
#define HW     16384
#define NHEAD  8
#define HD     64
#define MROWS  (NBATCH*SEQL)
#define LOG2E  1.4426950408889634f
#define NSPLIT 8
#define SPLEN  (HW / NSPLIT)

// ---------------- scratch (device globals; no allocation allowed) -------------
__device__ __half g_featsh[(size_t)NBATCH*HW*DIM];   // 256 MB
__device__ __half g_K2[(size_t)NBATCH*HW*DIM];       // 256 MB
__device__ __half g_V2[(size_t)NBATCH*HW*DIM];       // 256 MB
__device__ __half g_queryh[MROWS*DIM];
__device__ __half g_Wqh[DIM*DIM];
__device__ __half g_Wkh[DIM*DIM];
__device__ __half g_Wvh[DIM*DIM];
__device__ __half g_Wph[DIM*DIM];
__device__ __half g_W1h[DIM*DIM];
__device__ __half g_W2h[DIM*DIM];
__device__ __half g_Qh [MROWS*DIM];
__device__ __half g_AOh[MROWS*DIM];
__device__ __half g_Xh [MROWS*DIM];
__device__ __half g_Hh [MROWS*DIM];
__device__ float  g_X  [MROWS*DIM];
__device__ float  g_T  [MROWS*DIM];
__device__ float  g_PO[(size_t)NBATCH*NHEAD*NSPLIT*SEQL*HD];
__device__ float  g_PD[NBATCH*NHEAD*NSPLIT*128];

// ---------------- helpers ------------------------------------------------------
__device__ __forceinline__ uint32_t smem_u32(const void* p) {
    uint32_t a;
    asm("{ .reg .u64 t; cvta.to.shared.u64 t, %1; cvt.u32.u64 %0, t; }" : "=r"(a) : "l"(p));
    return a;
}
__device__ __forceinline__ void ldm4(uint32_t* r, uint32_t addr) {
    asm volatile("ldmatrix.sync.aligned.m8n8.x4.shared.b16 {%0,%1,%2,%3}, [%4];"
                 : "=r"(r[0]), "=r"(r[1]), "=r"(r[2]), "=r"(r[3]) : "r"(addr));
}
__device__ __forceinline__ void ldm4t(uint32_t* r, uint32_t addr) {
    asm volatile("ldmatrix.sync.aligned.m8n8.x4.trans.shared.b16 {%0,%1,%2,%3}, [%4];"
                 : "=r"(r[0]), "=r"(r[1]), "=r"(r[2]), "=r"(r[3]) : "r"(addr));
}
__device__ __forceinline__ void mmah(float* c, const uint32_t* a, uint32_t b0, uint32_t b1) {
    asm volatile("mma.sync.aligned.m16n8k16.row.col.f32.f16.f16.f32 "
                 "{%0,%1,%2,%3},{%4,%5,%6,%7},{%8,%9},{%0,%1,%2,%3};"
                 : "+f"(c[0]), "+f"(c[1]), "+f"(c[2]), "+f"(c[3])
                 : "r"(a[0]), "r"(a[1]), "r"(a[2]), "r"(a[3]), "r"(b0), "r"(b1));
}
__device__ __forceinline__ float ex2f(float x) {
    float y; asm("ex2.approx.f32 %0, %1;" : "=f"(y) : "f"(x)); return y;
}
// .cg: L2-only fills (no L1 allocation) — fills are streaming, reuse lives in smem
__device__ __forceinline__ void cpa16(uint32_t dst, const void* src) {
    asm volatile("cp.async.cg.shared.global [%0], [%1], 16;" :: "r"(dst), "l"(src));
}
#define CPCOMMIT() asm volatile("cp.async.commit_group;")
#define CPWAIT1()  asm volatile("cp.async.wait_group 1;")
#define CPWAIT0()  asm volatile("cp.async.wait_group 0;")

// ---------------- f32 -> f16 conversions ----------------------------------------
__global__ void cvt_h(const float* __restrict__ src, __half* __restrict__ dst, long long n)
{
    long long stride = (long long)gridDim.x * blockDim.x * 8;
    for (long long i = ((long long)blockIdx.x * blockDim.x + threadIdx.x) * 8;
         i < n; i += stride) {
        float4 a = *(const float4*)(src + i);
        float4 b = *(const float4*)(src + i + 4);
        __half2 h[4] = { __floats2half2_rn(a.x, a.y), __floats2half2_rn(a.z, a.w),
                         __floats2half2_rn(b.x, b.y), __floats2half2_rn(b.z, b.w) };
        *(uint4*)(dst + i) = *(uint4*)h;
    }
}

__global__ void cvt_h3(const float* __restrict__ s0, const float* __restrict__ s1,
                       const float* __restrict__ s2,
                       __half* __restrict__ d0, __half* __restrict__ d1,
                       __half* __restrict__ d2, long long n)
{
    const float* s = (blockIdx.y == 0) ? s0 : (blockIdx.y == 1) ? s1 : s2;
    __half*      d = (blockIdx.y == 0) ? d0 : (blockIdx.y == 1) ? d1 : d2;
    long long stride = (long long)gridDim.x * blockDim.x * 8;
    for (long long i = ((long long)blockIdx.x * blockDim.x + threadIdx.x) * 8;
         i < n; i += stride) {
        float4 a = *(const float4*)(s + i);
        float4 b = *(const float4*)(s + i + 4);
        __half2 h[4] = { __floats2half2_rn(a.x, a.y), __floats2half2_rn(a.z, a.w),
                         __floats2half2_rn(b.x, b.y), __floats2half2_rn(b.z, b.w) };
        *(uint4*)(d + i) = *(uint4*)h;
    }
}

// ---------------- half GEMM: BM=128, BN=128, BK=32, 3-stage cp.async ------------
// 256 threads, 8 warps in 4x2 grid of 32x64 tiles, occupancy 2.
#define GS2 40
#define GH_SMEM (3 * 2 * 128 * GS2 * 2)   // 61440 bytes

__global__ __launch_bounds__(256, 2)
void gemm_hh(const __half* __restrict__ A,
             const __half* __restrict__ B0, const __half* __restrict__ B1,
             void* __restrict__ C0v, void* __restrict__ C1v,
             int M, int ldc, int nsplitBlk, int outhalf,
             float alpha, const float* __restrict__ bias, int relu,
             long long sAz, long long sBz, long long sCz)
{
    extern __shared__ char smraw[];
    const uint32_t sa = smem_u32(smraw);
    const uint32_t sb = sa + 3u * 128 * GS2 * 2u;
    const int tid = threadIdx.x, lane = tid & 31, warp = tid >> 5;
    const int wm = warp >> 1, wn = warp & 1;
    const int g = lane >> 2, t = lane & 3;
    const int bm = blockIdx.y * 128;
    const int bx = blockIdx.x;
    const long long z = blockIdx.z;

    const __half* Bp; int bc;
    if (bx >= nsplitBlk) { Bp = B1; bc = (bx - nsplitBlk) * 128; }
    else                 { Bp = B0; bc = bx * 128; }

    const int r0l = tid >> 2;
    const int c8  = (tid & 3) * 8;
    int ar0 = bm + r0l;       if (ar0 > M - 1) ar0 = M - 1;
    int ar1 = bm + r0l + 64;  if (ar1 > M - 1) ar1 = M - 1;
    const __half* Ag0 = A  + z * sAz + (long long)ar0 * 512 + c8;
    const __half* Ag1 = A  + z * sAz + (long long)ar1 * 512 + c8;
    const __half* Bg0 = Bp + z * sBz + (long long)(bc + r0l) * 512 + c8;
    const __half* Bg1 = Bp + z * sBz + (long long)(bc + r0l + 64) * 512 + c8;
    const uint32_t da0 = sa + (uint32_t)(r0l * GS2 + c8) * 2u;
    const uint32_t da1 = sa + (uint32_t)((r0l + 64) * GS2 + c8) * 2u;
    const uint32_t db0 = sb + (uint32_t)(r0l * GS2 + c8) * 2u;
    const uint32_t db1 = sb + (uint32_t)((r0l + 64) * GS2 + c8) * 2u;
    const uint32_t bufb = 128 * GS2 * 2u;

    #define GLOAD(kt, st) do {                                   \
        uint32_t o = (uint32_t)(st) * bufb;                      \
        cpa16(da0 + o, Ag0 + (kt)*32);                           \
        cpa16(da1 + o, Ag1 + (kt)*32);                           \
        cpa16(db0 + o, Bg0 + (kt)*32);                           \
        cpa16(db1 + o, Bg1 + (kt)*32);                           \
        CPCOMMIT();                                              \
    } while (0)

    float acc[2][8][4];
    #pragma unroll
    for (int i = 0; i < 2; ++i)
        #pragma unroll
        for (int j = 0; j < 8; ++j)
            #pragma unroll
            for (int k = 0; k < 4; ++k) acc[i][j][k] = 0.f;

    GLOAD(0, 0);
    GLOAD(1, 1);

    #pragma unroll 1
    for (int kt = 0; kt < 16; ++kt) {
        if (kt < 15) CPWAIT1(); else CPWAIT0();
        __syncthreads();
        if (kt < 14) {
            int st = (kt + 2) % 3;
            GLOAD(kt + 2, st);
        }
        int sc = kt % 3;
        const uint32_t ab = sa + sc * bufb;
        const uint32_t bb = sb + sc * bufb;
        #pragma unroll
        for (int kk = 0; kk < 2; ++kk) {
            uint32_t afr[2][4];
            #pragma unroll
            for (int fm = 0; fm < 2; ++fm)
                ldm4(afr[fm], ab + (uint32_t)((wm*32 + fm*16 + (lane & 15))*GS2
                                              + kk*16 + (lane >> 4)*8) * 2u);
            #pragma unroll
            for (int nb = 0; nb < 4; ++nb) {
                uint32_t bfr[4];
                ldm4(bfr, bb + (uint32_t)((wn*64 + nb*16 + (lane >> 4)*8 + (lane & 7))*GS2
                                          + kk*16 + ((lane >> 3) & 1)*8) * 2u);
                #pragma unroll
                for (int fm = 0; fm < 2; ++fm) {
                    mmah(acc[fm][2*nb],     afr[fm], bfr[0], bfr[1]);
                    mmah(acc[fm][2*nb + 1], afr[fm], bfr[2], bfr[3]);
                }
            }
        }
    }

    float*  Cf = (bx >= nsplitBlk) ? (float*)C1v  : (float*)C0v;
    __half* Ch = (bx >= nsplitBlk) ? (__half*)C1v : (__half*)C0v;
    Cf += z * sCz; Ch += z * sCz;
    #pragma unroll
    for (int fm = 0; fm < 2; ++fm) {
        int r0 = bm + wm*32 + fm*16 + g;
        int r1 = r0 + 8;
        #pragma unroll
        for (int fn = 0; fn < 8; ++fn) {
            int c = bc + wn*64 + fn*8 + 2*t;
            float b0v = 0.f, b1v = 0.f;
            if (bias) { b0v = bias[c]; b1v = bias[c + 1]; }
            float v0 = acc[fm][fn][0]*alpha + b0v;
            float v1 = acc[fm][fn][1]*alpha + b1v;
            float v2 = acc[fm][fn][2]*alpha + b0v;
            float v3 = acc[fm][fn][3]*alpha + b1v;
            if (relu) {
                v0 = fmaxf(v0, 0.f); v1 = fmaxf(v1, 0.f);
                v2 = fmaxf(v2, 0.f); v3 = fmaxf(v3, 0.f);
            }
            if (outhalf) {
                if (r0 < M) *(__half2*)&Ch[(long long)r0*ldc + c] = __floats2half2_rn(v0, v1);
                if (r1 < M) *(__half2*)&Ch[(long long)r1*ldc + c] = __floats2half2_rn(v2, v3);
            } else {
                if (r0 < M) *(float2*)&Cf[(long long)r0*ldc + c] = make_float2(v0, v1);
                if (r1 < M) *(float2*)&Cf[(long long)r1*ldc + c] = make_float2(v2, v3);
            }
        }
    }
}

// ---------------- attention: fp16 flash, split-K x8, 3-stage cp.async K/V -------
#define AQS 72
#define NCH (SPLEN / 64)    // 32 chunks per split
#define ATTN_SMEM ((128 + 3*64 + 3*64 + 128) * AQS * 2 + (128 + 256) * 4)  // 93696

__global__ __launch_bounds__(256, 2)
void attn_k()
{
    extern __shared__ char smraw[];
    __half* Qs = (__half*)smraw;          // 128*AQS
    __half* Ks = Qs + 128*AQS;            // 3 stages x 64*AQS
    __half* Vs = Ks + 3*64*AQS;           // 3 stages x 64*AQS
    __half* Ps = Vs + 3*64*AQS;           // 128*AQS
    float* denom = (float*)(Ps + 128*AQS);   // 128
    float* rsum2 = denom + 128;              // 256 (two wn banks)

    const int x = blockIdx.x;
    const int split = x & (NSPLIT - 1), bh = x >> 3;
    const int b = bh >> 3, h = bh & 7;
    const int tid = threadIdx.x, lane = tid & 31, warp = tid >> 5;
    const int g = lane >> 2, t = lane & 3;
    const int wm = warp >> 1, wn = warp & 1;
    const int k0 = split * SPLEN;

    const uint32_t qb = smem_u32(Qs), kb = smem_u32(Ks);
    const uint32_t vb = smem_u32(Vs), pb = smem_u32(Ps);
    const uint32_t stageB = 64 * AQS * 2u;

    const int rr = tid >> 2, cc = (tid & 3) * 16;
    const uint32_t dk = kb + (uint32_t)(rr * AQS + cc) * 2u;
    const uint32_t dv = vb + (uint32_t)(rr * AQS + cc) * 2u;

    #define ALOAD(ci, st) do {                                                  \
        long long off = ((long long)(b*HW + k0 + (ci)*64 + rr))*DIM + h*HD + cc;\
        uint32_t o = (uint32_t)(st) * stageB;                                   \
        cpa16(dk + o,      g_K2 + off);                                         \
        cpa16(dk + o + 16, g_K2 + off + 8);                                     \
        cpa16(dv + o,      g_V2 + off);                                         \
        cpa16(dv + o + 16, g_V2 + off + 8);                                     \
        CPCOMMIT();                                                             \
    } while (0)

    // Q tile [128 x 64] half; zero rows >= 100
    {
        int r = tid >> 1, c0 = (tid & 1) * 32;
        const __half* src = g_Qh + (long long)(b*SEQL + (r < SEQL ? r : 0))*DIM + h*HD + c0;
        uint4 z4 = make_uint4(0, 0, 0, 0);
        #pragma unroll
        for (int j = 0; j < 4; ++j) {
            uint4 v = (r < SEQL) ? ((const uint4*)src)[j] : z4;
            *(uint4*)&Qs[r*AQS + c0 + j*8] = v;
        }
    }
    if (tid < 128) denom[tid] = 0.f;

    float oacc[2][4][4];
    #pragma unroll
    for (int i = 0; i < 2; ++i)
        #pragma unroll
        for (int j = 0; j < 4; ++j)
            #pragma unroll
            for (int k = 0; k < 4; ++k) oacc[i][j][k] = 0.f;

    ALOAD(0, 0);
    ALOAD(1, 1);

    #pragma unroll 1
    for (int ci = 0; ci < NCH; ++ci) {
        const int st = ci % 3;
        if (ci < NCH - 1) CPWAIT1(); else CPWAIT0();
        __syncthreads();   // chunk ci visible; prior iter's PV done CTA-wide
        if (ci + 2 < NCH) ALOAD(ci + 2, (ci + 2) % 3);

        // S = Q @ K^T  (warp: 32 q-rows x 32 keys)
        const uint32_t kbs = kb + st * stageB;
        float sacc[2][4][4];
        #pragma unroll
        for (int i = 0; i < 2; ++i)
            #pragma unroll
            for (int j = 0; j < 4; ++j)
                #pragma unroll
                for (int k = 0; k < 4; ++k) sacc[i][j][k] = 0.f;
        #pragma unroll
        for (int ks = 0; ks < 4; ++ks) {
            uint32_t afr[2][4];
            #pragma unroll
            for (int fm = 0; fm < 2; ++fm)
                ldm4(afr[fm], qb + (uint32_t)((wm*32 + fm*16 + (lane & 15))*AQS
                                              + ks*16 + (lane >> 4)*8) * 2u);
            #pragma unroll
            for (int nb = 0; nb < 2; ++nb) {
                uint32_t bfr[4];
                ldm4(bfr, kbs + (uint32_t)((wn*32 + nb*16 + (lane >> 4)*8 + (lane & 7))*AQS
                                           + ks*16 + ((lane >> 3) & 1)*8) * 2u);
                #pragma unroll
                for (int fm = 0; fm < 2; ++fm) {
                    mmah(sacc[fm][2*nb],     afr[fm], bfr[0], bfr[1]);
                    mmah(sacc[fm][2*nb + 1], afr[fm], bfr[2], bfr[3]);
                }
            }
        }

        // P = exp(S), per-wn row-sum banks (no atomics)
        #pragma unroll
        for (int fm = 0; fm < 2; ++fm) {
            float rs0 = 0.f, rs1 = 0.f;
            int row0 = wm*32 + fm*16 + g;
            #pragma unroll
            for (int fn = 0; fn < 4; ++fn) {
                float p0 = ex2f(sacc[fm][fn][0] * LOG2E);
                float p1 = ex2f(sacc[fm][fn][1] * LOG2E);
                float p2 = ex2f(sacc[fm][fn][2] * LOG2E);
                float p3 = ex2f(sacc[fm][fn][3] * LOG2E);
                rs0 += p0 + p1; rs1 += p2 + p3;
                int c = wn*32 + fn*8 + 2*t;
                *(__half2*)&Ps[row0*AQS + c]       = __floats2half2_rn(p0, p1);
                *(__half2*)&Ps[(row0 + 8)*AQS + c] = __floats2half2_rn(p2, p3);
            }
            rs0 += __shfl_xor_sync(0xffffffffu, rs0, 1);
            rs0 += __shfl_xor_sync(0xffffffffu, rs0, 2);
            rs1 += __shfl_xor_sync(0xffffffffu, rs1, 1);
            rs1 += __shfl_xor_sync(0xffffffffu, rs1, 2);
            if (t == 0) {
                rsum2[wn*128 + row0]     = rs0;
                rsum2[wn*128 + row0 + 8] = rs1;
            }
        }
        __syncthreads();   // Ps + rsum2 complete
        if (tid < 128) denom[tid] += rsum2[tid] + rsum2[128 + tid];

        // O += P @ V; next iteration's first barrier orders stage reuse
        const uint32_t vbs = vb + st * stageB;
        #pragma unroll
        for (int kk = 0; kk < 4; ++kk) {
            uint32_t afr[2][4];
            #pragma unroll
            for (int fm = 0; fm < 2; ++fm)
                ldm4(afr[fm], pb + (uint32_t)((wm*32 + fm*16 + (lane & 15))*AQS
                                              + kk*16 + (lane >> 4)*8) * 2u);
            #pragma unroll
            for (int nb = 0; nb < 2; ++nb) {
                uint32_t bfr[4];
                ldm4t(bfr, vbs + (uint32_t)((kk*16 + ((lane >> 3) & 1)*8 + (lane & 7))*AQS
                                            + wn*32 + nb*16 + (lane >> 4)*8) * 2u);
                #pragma unroll
                for (int fm = 0; fm < 2; ++fm) {
                    mmah(oacc[fm][2*nb],     afr[fm], bfr[0], bfr[1]);
                    mmah(oacc[fm][2*nb + 1], afr[fm], bfr[2], bfr[3]);
                }
            }
        }
    }

    #pragma unroll
    for (int fm = 0; fm < 2; ++fm) {
        int row0 = wm*32 + fm*16 + g;
        int row1 = row0 + 8;
        #pragma unroll
        for (int fn = 0; fn < 4; ++fn) {
            int c = wn*32 + fn*8 + 2*t;
            if (row0 < SEQL)
                *(float2*)&g_PO[((long long)x*SEQL + row0)*HD + c] =
                    make_float2(oacc[fm][fn][0], oacc[fm][fn][1]);
            if (row1 < SEQL)
                *(float2*)&g_PO[((long long)x*SEQL + row1)*HD + c] =
                    make_float2(oacc[fm][fn][2], oacc[fm][fn][3]);
        }
    }
    if (tid < 128) g_PD[x*128 + tid] = denom[tid];
}

// ---------------- attention reduce ----------------------------------------------
__global__ void attn_reduce()
{
    const int row = blockIdx.x;
    const int b = row / SEQL, l = row % SEQL;
    const int c = threadIdx.x;             // 0..511
    const int h = c >> 6, d = c & 63;
    const int xb = (b * NHEAD + h) * NSPLIT;
    float num = 0.f, den = 0.f;
    #pragma unroll
    for (int s = 0; s < NSPLIT; ++s) {
        num += g_PO[((long long)(xb + s)*SEQL + l)*HD + d];
        den += g_PD[(xb + s)*128 + l];
    }
    g_AOh[(long long)row * DIM + c] = __float2half_rn(num / den);
}

// ---------------- LayerNorm(a + t) -----------------------------------------------
__global__ void ln_add_k(const float* __restrict__ a, const float* __restrict__ tt,
                         const float* __restrict__ w, const float* __restrict__ bb,
                         float* __restrict__ o, __half* __restrict__ oh)
{
    __shared__ float red[4];
    __shared__ float smu, sinv;
    int row = blockIdx.x, tid = threadIdx.x;   // 128 threads
    const float* pa = a  + (long long)row * DIM;
    const float* pt = tt + (long long)row * DIM;
    float v[4]; float s = 0.f;
    #pragma unroll
    for (int i = 0; i < 4; ++i) {
        v[i] = pa[tid + i*128] + pt[tid + i*128];
        s += v[i];
    }
    #pragma unroll
    for (int off = 16; off; off >>= 1) s += __shfl_xor_sync(0xffffffffu, s, off);
    if ((tid & 31) == 0) red[tid >> 5] = s;
    __syncthreads();
    if (tid == 0) smu = (red[0] + red[1] + red[2] + red[3]) * (1.f / 512.f);
    __syncthreads();
    float mu = smu; float s2 = 0.f;
    #pragma unroll
    for (int i = 0; i < 4; ++i) { float d = v[i] - mu; s2 += d * d; }
    #pragma unroll
    for (int off = 16; off; off >>= 1) s2 += __shfl_xor_sync(0xffffffffu, s2, off);
    if ((tid & 31) == 0) red[tid >> 5] = s2;
    __syncthreads();
    if (tid == 0) sinv = rsqrtf((red[0] + red[1] + red[2] + red[3]) * (1.f / 512.f) + 1e-5f);
    __syncthreads();
    float inv = sinv;
    #pragma unroll
    for (int i = 0; i < 4; ++i) {
        int c = tid + i*128;
        float y = (v[i] - mu) * inv * w[c] + bb[c];
        if (o)  o [(long long)row * DIM + c] = y;
        if (oh) oh[(long long)row * DIM + c] = __float2half_rn(y);
    }
}

// ---------------- launch -----------------------------------------------------------
extern "C" void kernel_launch(void* const* d_in, const int* in_sizes, int n_in,
                              void* d_out, int out_size)
{
    const float* query = (const float*)d_in[0];
    const float* feats = (const float*)d_in[1];
    const float* Wq    = (const float*)d_in[2];
    const float* Wk    = (const float*)d_in[3];
    const float* Wv    = (const float*)d_in[4];
    const float* Wp    = (const float*)d_in[5];
    const float* bp    = (const float*)d_in[6];
    const float* W1    = (const float*)d_in[7];
    const float* b1    = (const float*)d_in[8];
    const float* W2    = (const float*)d_in[9];
    const float* b2    = (const float*)d_in[10];
    const float* ln0w  = (const float*)d_in[11];
    const float* ln0b  = (const float*)d_in[12];
    const float* ln2w  = (const float*)d_in[13];
    const float* ln2b  = (const float*)d_in[14];
    float* out = (float*)d_out;

    __half *pFh, *pK2, *pV2, *pQryh, *pWqh, *pWkh, *pWvh, *pWph, *pW1h, *pW2h;
    __half *pQh, *pAOh, *pXh, *pHh;
    float *pX, *pT;
    cudaGetSymbolAddress((void**)&pFh,   g_featsh);
    cudaGetSymbolAddress((void**)&pK2,   g_K2);
    cudaGetSymbolAddress((void**)&pV2,   g_V2);
    cudaGetSymbolAddress((void**)&pQryh, g_queryh);
    cudaGetSymbolAddress((void**)&pWqh,  g_Wqh);
    cudaGetSymbolAddress((void**)&pWkh,  g_Wkh);
    cudaGetSymbolAddress((void**)&pWvh,  g_Wvh);
    cudaGetSymbolAddress((void**)&pWph,  g_Wph);
    cudaGetSymbolAddress((void**)&pW1h,  g_W1h);
    cudaGetSymbolAddress((void**)&pW2h,  g_W2h);
    cudaGetSymbolAddress((void**)&pQh,   g_Qh);
    cudaGetSymbolAddress((void**)&pAOh,  g_AOh);
    cudaGetSymbolAddress((void**)&pXh,   g_Xh);
    cudaGetSymbolAddress((void**)&pHh,   g_Hh);
    cudaGetSymbolAddress((void**)&pX,    g_X);
    cudaGetSymbolAddress((void**)&pT,    g_T);

    cudaFuncSetAttribute(gemm_hh, cudaFuncAttributeMaxDynamicSharedMemorySize, GH_SMEM);
    cudaFuncSetAttribute(attn_k,  cudaFuncAttributeMaxDynamicSharedMemorySize, ATTN_SMEM);

    // 0. feats -> half
    cvt_h<<<8192, 256>>>(feats, pFh, (long long)NBATCH*HW*DIM);
    // 1. Wq,Wk,Wv -> half
    cvt_h3<<<dim3(64, 3), 256>>>(Wq, Wk, Wv, pWqh, pWkh, pWvh, DIM*DIM);
    // 2. fused K,V projections -> g_K2, g_V2 (half)
    gemm_hh<<<dim3(8, 2048, 1), 256, GH_SMEM>>>(pFh, pWkh, pWvh, pK2, pV2,
                                                NBATCH*HW, DIM, 4, 1, 1.f, nullptr, 0,
                                                0, 0, 0);
    // 3. query -> half
    cvt_h<<<400, 256>>>(query, pQryh, (long long)MROWS*DIM);
    // 4. Wp,W1,W2 -> half
    cvt_h3<<<dim3(64, 3), 256>>>(Wp, W1, W2, pWph, pW1h, pW2h, DIM*DIM);
    // 5. q = 0.125 * query @ Wq^T -> g_Qh
    gemm_hh<<<dim3(4, 13, 1), 256, GH_SMEM>>>(pQryh, pWqh, pWqh, pQh, pQh,
                                              MROWS, DIM, 999, 1, 0.125f, nullptr, 0,
                                              0, 0, 0);
    // 6-7. attention partials + reduce -> g_AOh
    attn_k<<<NBATCH * NHEAD * NSPLIT, 256, ATTN_SMEM>>>();
    attn_reduce<<<MROWS, 512>>>();
    // 8. mask = q @ K^T per batch -> d_out tail (f32)
    gemm_hh<<<dim3(HW/128, 1, NBATCH), 256, GH_SMEM>>>(pQh, pK2, pK2,
                                              out + (long long)MROWS*DIM,
                                              out + (long long)MROWS*DIM,
                                              SEQL, HW, 999, 0, 1.f, nullptr, 0,
                                              (long long)SEQL*DIM,
                                              (long long)HW*DIM,
                                              (long long)SEQL*HW);
    // 9. attn_out @ Wp^T + bp -> g_T (f32)
    gemm_hh<<<dim3(4, 13, 1), 256, GH_SMEM>>>(pAOh, pWph, pWph, pT, pT,
                                              MROWS, DIM, 999, 0, 1.f, bp, 0, 0, 0, 0);
    // 10. x = LN(query + t)
    ln_add_k<<<MROWS, 128>>>(query, pT, ln0w, ln0b, pX, pXh);
    // 11. h = relu(x @ W1^T + b1) -> g_Hh
    gemm_hh<<<dim3(4, 13, 1), 256, GH_SMEM>>>(pXh, pW1h, pW1h, pHh, pHh,
                                              MROWS, DIM, 999, 1, 1.f, b1, 1, 0, 0, 0);
    // 12. f = h @ W2^T + b2 -> g_T
    gemm_hh<<<dim3(4, 13, 1), 256, GH_SMEM>>>(pHh, pW2h, pW2h, pT, pT,
                                              MROWS, DIM, 999, 0, 1.f, b2, 0, 0, 0, 0);
    // 13. y = LN(x + f) -> d_out head
    ln_add_k<<<MROWS, 128>>>(pX, pT, ln2w, ln2b, out, nullptr);
}

// round 16
// speedup vs baseline: 1.0370x; 1.0370x over previous
#include <cuda_runtime.h>
#include <cuda_fp16.h>
#include <stdint.h>

#define NBATCH 16
#define SEQL   100
#define DIM    512
#define HW     16384
#define NHEAD  8
#define HD     64
#define MROWS  (NBATCH*SEQL)
#define LOG2E  1.4426950408889634f
#define NSPLIT 8
#define SPLEN  (HW / NSPLIT)

// ---------------- scratch (device globals; no allocation allowed) -------------
__device__ __half g_featsh[(size_t)NBATCH*HW*DIM];   // 256 MB
__device__ __half g_K2[(size_t)NBATCH*HW*DIM];       // 256 MB
__device__ __half g_V2[(size_t)NBATCH*HW*DIM];       // 256 MB
__device__ __half g_queryh[MROWS*DIM];
__device__ __half g_Wqh[DIM*DIM];
__device__ __half g_Wkh[DIM*DIM];
__device__ __half g_Wvh[DIM*DIM];
__device__ __half g_Wph[DIM*DIM];
__device__ __half g_W1h[DIM*DIM];
__device__ __half g_W2h[DIM*DIM];
__device__ __half g_Qh [MROWS*DIM];
__device__ __half g_AOh[MROWS*DIM];
__device__ __half g_Xh [MROWS*DIM];
__device__ __half g_Hh [MROWS*DIM];
__device__ float  g_X  [MROWS*DIM];
__device__ float  g_T  [MROWS*DIM];
__device__ float  g_PO[(size_t)NBATCH*NHEAD*NSPLIT*SEQL*HD];
__device__ float  g_PD[NBATCH*NHEAD*NSPLIT*128];

// ---------------- helpers ------------------------------------------------------
__device__ __forceinline__ uint32_t smem_u32(const void* p) {
    uint32_t a;
    asm("{ .reg .u64 t; cvta.to.shared.u64 t, %1; cvt.u32.u64 %0, t; }" : "=r"(a) : "l"(p));
    return a;
}
__device__ __forceinline__ void ldm4(uint32_t* r, uint32_t addr) {
    asm volatile("ldmatrix.sync.aligned.m8n8.x4.shared.b16 {%0,%1,%2,%3}, [%4];"
                 : "=r"(r[0]), "=r"(r[1]), "=r"(r[2]), "=r"(r[3]) : "r"(addr));
}
__device__ __forceinline__ void ldm4t(uint32_t* r, uint32_t addr) {
    asm volatile("ldmatrix.sync.aligned.m8n8.x4.trans.shared.b16 {%0,%1,%2,%3}, [%4];"
                 : "=r"(r[0]), "=r"(r[1]), "=r"(r[2]), "=r"(r[3]) : "r"(addr));
}
__device__ __forceinline__ void mmah(float* c, const uint32_t* a, uint32_t b0, uint32_t b1) {
    asm volatile("mma.sync.aligned.m16n8k16.row.col.f32.f16.f16.f32 "
                 "{%0,%1,%2,%3},{%4,%5,%6,%7},{%8,%9},{%0,%1,%2,%3};"
                 : "+f"(c[0]), "+f"(c[1]), "+f"(c[2]), "+f"(c[3])
                 : "r"(a[0]), "r"(a[1]), "r"(a[2]), "r"(a[3]), "r"(b0), "r"(b1));
}
__device__ __forceinline__ float ex2f(float x) {
    float y; asm("ex2.approx.f32 %0, %1;" : "=f"(y) : "f"(x)); return y;
}
// .ca (measured best: .cg regressed in R15)
__device__ __forceinline__ void cpa16(uint32_t dst, const void* src) {
    asm volatile("cp.async.ca.shared.global [%0], [%1], 16;" :: "r"(dst), "l"(src));
}
#define CPCOMMIT() asm volatile("cp.async.commit_group;")
#define CPWAIT1()  asm volatile("cp.async.wait_group 1;")
#define CPWAIT0()  asm volatile("cp.async.wait_group 0;")

// ---------------- f32 -> f16 conversions ----------------------------------------
__global__ void cvt_h(const float* __restrict__ src, __half* __restrict__ dst, long long n)
{
    long long stride = (long long)gridDim.x * blockDim.x * 8;
    for (long long i = ((long long)blockIdx.x * blockDim.x + threadIdx.x) * 8;
         i < n; i += stride) {
        float4 a = *(const float4*)(src + i);
        float4 b = *(const float4*)(src + i + 4);
        __half2 h[4] = { __floats2half2_rn(a.x, a.y), __floats2half2_rn(a.z, a.w),
                         __floats2half2_rn(b.x, b.y), __floats2half2_rn(b.z, b.w) };
        *(uint4*)(dst + i) = *(uint4*)h;
    }
}

__global__ void cvt_h3(const float* __restrict__ s0, const float* __restrict__ s1,
                       const float* __restrict__ s2,
                       __half* __restrict__ d0, __half* __restrict__ d1,
                       __half* __restrict__ d2, long long n)
{
    const float* s = (blockIdx.y == 0) ? s0 : (blockIdx.y == 1) ? s1 : s2;
    __half*      d = (blockIdx.y == 0) ? d0 : (blockIdx.y == 1) ? d1 : d2;
    long long stride = (long long)gridDim.x * blockDim.x * 8;
    for (long long i = ((long long)blockIdx.x * blockDim.x + threadIdx.x) * 8;
         i < n; i += stride) {
        float4 a = *(const float4*)(s + i);
        float4 b = *(const float4*)(s + i + 4);
        __half2 h[4] = { __floats2half2_rn(a.x, a.y), __floats2half2_rn(a.z, a.w),
                         __floats2half2_rn(b.x, b.y), __floats2half2_rn(b.z, b.w) };
        *(uint4*)(d + i) = *(uint4*)h;
    }
}

// ---------------- half GEMM: BM=128, BN=128, BK=32, 3-stage cp.async ------------
// 256 threads, 8 warps in 4x2 grid of 32x64 tiles, occupancy 2. (champion config)
#define GS2 40
#define GH_SMEM (3 * 2 * 128 * GS2 * 2)   // 61440 bytes

__global__ __launch_bounds__(256, 2)
void gemm_hh(const __half* __restrict__ A,
             const __half* __restrict__ B0, const __half* __restrict__ B1,
             void* __restrict__ C0v, void* __restrict__ C1v,
             int M, int ldc, int nsplitBlk, int outhalf,
             float alpha, const float* __restrict__ bias, int relu,
             long long sAz, long long sBz, long long sCz)
{
    extern __shared__ char smraw[];
    const uint32_t sa = smem_u32(smraw);
    const uint32_t sb = sa + 3u * 128 * GS2 * 2u;
    const int tid = threadIdx.x, lane = tid & 31, warp = tid >> 5;
    const int wm = warp >> 1, wn = warp & 1;
    const int g = lane >> 2, t = lane & 3;
    const int bm = blockIdx.y * 128;
    const int bx = blockIdx.x;
    const long long z = blockIdx.z;

    const __half* Bp; int bc;
    if (bx >= nsplitBlk) { Bp = B1; bc = (bx - nsplitBlk) * 128; }
    else                 { Bp = B0; bc = bx * 128; }

    const int r0l = tid >> 2;
    const int c8  = (tid & 3) * 8;
    int ar0 = bm + r0l;       if (ar0 > M - 1) ar0 = M - 1;
    int ar1 = bm + r0l + 64;  if (ar1 > M - 1) ar1 = M - 1;
    const __half* Ag0 = A  + z * sAz + (long long)ar0 * 512 + c8;
    const __half* Ag1 = A  + z * sAz + (long long)ar1 * 512 + c8;
    const __half* Bg0 = Bp + z * sBz + (long long)(bc + r0l) * 512 + c8;
    const __half* Bg1 = Bp + z * sBz + (long long)(bc + r0l + 64) * 512 + c8;
    const uint32_t da0 = sa + (uint32_t)(r0l * GS2 + c8) * 2u;
    const uint32_t da1 = sa + (uint32_t)((r0l + 64) * GS2 + c8) * 2u;
    const uint32_t db0 = sb + (uint32_t)(r0l * GS2 + c8) * 2u;
    const uint32_t db1 = sb + (uint32_t)((r0l + 64) * GS2 + c8) * 2u;
    const uint32_t bufb = 128 * GS2 * 2u;

    #define GLOAD(kt, st) do {                                   \
        uint32_t o = (uint32_t)(st) * bufb;                      \
        cpa16(da0 + o, Ag0 + (kt)*32);                           \
        cpa16(da1 + o, Ag1 + (kt)*32);                           \
        cpa16(db0 + o, Bg0 + (kt)*32);                           \
        cpa16(db1 + o, Bg1 + (kt)*32);                           \
        CPCOMMIT();                                              \
    } while (0)

    float acc[2][8][4];
    #pragma unroll
    for (int i = 0; i < 2; ++i)
        #pragma unroll
        for (int j = 0; j < 8; ++j)
            #pragma unroll
            for (int k = 0; k < 4; ++k) acc[i][j][k] = 0.f;

    GLOAD(0, 0);
    GLOAD(1, 1);

    #pragma unroll 1
    for (int kt = 0; kt < 16; ++kt) {
        if (kt < 15) CPWAIT1(); else CPWAIT0();
        __syncthreads();
        if (kt < 14) {
            int st = (kt + 2) % 3;
            GLOAD(kt + 2, st);
        }
        int sc = kt % 3;
        const uint32_t ab = sa + sc * bufb;
        const uint32_t bb = sb + sc * bufb;
        #pragma unroll
        for (int kk = 0; kk < 2; ++kk) {
            uint32_t afr[2][4];
            #pragma unroll
            for (int fm = 0; fm < 2; ++fm)
                ldm4(afr[fm], ab + (uint32_t)((wm*32 + fm*16 + (lane & 15))*GS2
                                              + kk*16 + (lane >> 4)*8) * 2u);
            #pragma unroll
            for (int nb = 0; nb < 4; ++nb) {
                uint32_t bfr[4];
                ldm4(bfr, bb + (uint32_t)((wn*64 + nb*16 + (lane >> 4)*8 + (lane & 7))*GS2
                                          + kk*16 + ((lane >> 3) & 1)*8) * 2u);
                #pragma unroll
                for (int fm = 0; fm < 2; ++fm) {
                    mmah(acc[fm][2*nb],     afr[fm], bfr[0], bfr[1]);
                    mmah(acc[fm][2*nb + 1], afr[fm], bfr[2], bfr[3]);
                }
            }
        }
    }

    float*  Cf = (bx >= nsplitBlk) ? (float*)C1v  : (float*)C0v;
    __half* Ch = (bx >= nsplitBlk) ? (__half*)C1v : (__half*)C0v;
    Cf += z * sCz; Ch += z * sCz;
    #pragma unroll
    for (int fm = 0; fm < 2; ++fm) {
        int r0 = bm + wm*32 + fm*16 + g;
        int r1 = r0 + 8;
        #pragma unroll
        for (int fn = 0; fn < 8; ++fn) {
            int c = bc + wn*64 + fn*8 + 2*t;
            float b0v = 0.f, b1v = 0.f;
            if (bias) { b0v = bias[c]; b1v = bias[c + 1]; }
            float v0 = acc[fm][fn][0]*alpha + b0v;
            float v1 = acc[fm][fn][1]*alpha + b1v;
            float v2 = acc[fm][fn][2]*alpha + b0v;
            float v3 = acc[fm][fn][3]*alpha + b1v;
            if (relu) {
                v0 = fmaxf(v0, 0.f); v1 = fmaxf(v1, 0.f);
                v2 = fmaxf(v2, 0.f); v3 = fmaxf(v3, 0.f);
            }
            if (outhalf) {
                if (r0 < M) *(__half2*)&Ch[(long long)r0*ldc + c] = __floats2half2_rn(v0, v1);
                if (r1 < M) *(__half2*)&Ch[(long long)r1*ldc + c] = __floats2half2_rn(v2, v3);
            } else {
                if (r0 < M) *(float2*)&Cf[(long long)r0*ldc + c] = make_float2(v0, v1);
                if (r1 < M) *(float2*)&Cf[(long long)r1*ldc + c] = make_float2(v2, v3);
            }
        }
    }
}

// ---------------- attention: fp16 flash, split-K x8, 3-stage cp.async K/V -------
#define AQS 72
#define NCH (SPLEN / 64)    // 32 chunks per split
#define ATTN_SMEM ((128 + 3*64 + 3*64 + 128) * AQS * 2 + 256 * 4)

__global__ __launch_bounds__(256, 2)
void attn_k()
{
    extern __shared__ char smraw[];
    __half* Qs = (__half*)smraw;          // 128*AQS
    __half* Ks = Qs + 128*AQS;            // 3 stages x 64*AQS
    __half* Vs = Ks + 3*64*AQS;           // 3 stages x 64*AQS
    __half* Ps = Vs + 3*64*AQS;           // 128*AQS
    float* rsum2 = (float*)(Ps + 128*AQS);   // 256 (two wn banks, used once at end)

    const int x = blockIdx.x;
    const int split = x & (NSPLIT - 1), bh = x >> 3;
    const int b = bh >> 3, h = bh & 7;
    const int tid = threadIdx.x, lane = tid & 31, warp = tid >> 5;
    const int g = lane >> 2, t = lane & 3;
    const int wm = warp >> 1, wn = warp & 1;
    const int k0 = split * SPLEN;

    const uint32_t qb = smem_u32(Qs), kb = smem_u32(Ks);
    const uint32_t vb = smem_u32(Vs), pb = smem_u32(Ps);
    const uint32_t stageB = 64 * AQS * 2u;

    const int rr = tid >> 2, cc = (tid & 3) * 16;
    const uint32_t dk = kb + (uint32_t)(rr * AQS + cc) * 2u;
    const uint32_t dv = vb + (uint32_t)(rr * AQS + cc) * 2u;

    #define ALOAD(ci, st) do {                                                  \
        long long off = ((long long)(b*HW + k0 + (ci)*64 + rr))*DIM + h*HD + cc;\
        uint32_t o = (uint32_t)(st) * stageB;                                   \
        cpa16(dk + o,      g_K2 + off);                                         \
        cpa16(dk + o + 16, g_K2 + off + 8);                                     \
        cpa16(dv + o,      g_V2 + off);                                         \
        cpa16(dv + o + 16, g_V2 + off + 8);                                     \
        CPCOMMIT();                                                             \
    } while (0)

    // Q tile [128 x 64] half; zero rows >= 100
    {
        int r = tid >> 1, c0 = (tid & 1) * 32;
        const __half* src = g_Qh + (long long)(b*SEQL + (r < SEQL ? r : 0))*DIM + h*HD + c0;
        uint4 z4 = make_uint4(0, 0, 0, 0);
        #pragma unroll
        for (int j = 0; j < 4; ++j) {
            uint4 v = (r < SEQL) ? ((const uint4*)src)[j] : z4;
            *(uint4*)&Qs[r*AQS + c0 + j*8] = v;
        }
    }

    float oacc[2][4][4];
    #pragma unroll
    for (int i = 0; i < 2; ++i)
        #pragma unroll
        for (int j = 0; j < 4; ++j)
            #pragma unroll
            for (int k = 0; k < 4; ++k) oacc[i][j][k] = 0.f;

    // running denominators (this warp's wn key-half) for rows fm*16+g, +8
    float dreg[2][2] = {{0.f, 0.f}, {0.f, 0.f}};

    ALOAD(0, 0);
    ALOAD(1, 1);

    #pragma unroll 1
    for (int ci = 0; ci < NCH; ++ci) {
        const int st = ci % 3;
        if (ci < NCH - 1) CPWAIT1(); else CPWAIT0();
        __syncthreads();   // chunk ci visible; prior iter's PV done CTA-wide
        if (ci + 2 < NCH) ALOAD(ci + 2, (ci + 2) % 3);

        // S = Q @ K^T  (warp: 32 q-rows x 32 keys)
        const uint32_t kbs = kb + st * stageB;
        float sacc[2][4][4];
        #pragma unroll
        for (int i = 0; i < 2; ++i)
            #pragma unroll
            for (int j = 0; j < 4; ++j)
                #pragma unroll
                for (int k = 0; k < 4; ++k) sacc[i][j][k] = 0.f;
        #pragma unroll
        for (int ks = 0; ks < 4; ++ks) {
            uint32_t afr[2][4];
            #pragma unroll
            for (int fm = 0; fm < 2; ++fm)
                ldm4(afr[fm], qb + (uint32_t)((wm*32 + fm*16 + (lane & 15))*AQS
                                              + ks*16 + (lane >> 4)*8) * 2u);
            #pragma unroll
            for (int nb = 0; nb < 2; ++nb) {
                uint32_t bfr[4];
                ldm4(bfr, kbs + (uint32_t)((wn*32 + nb*16 + (lane >> 4)*8 + (lane & 7))*AQS
                                           + ks*16 + ((lane >> 3) & 1)*8) * 2u);
                #pragma unroll
                for (int fm = 0; fm < 2; ++fm) {
                    mmah(sacc[fm][2*nb],     afr[fm], bfr[0], bfr[1]);
                    mmah(sacc[fm][2*nb + 1], afr[fm], bfr[2], bfr[3]);
                }
            }
        }

        // P = exp(S) -> Ps; accumulate row sums in registers
        #pragma unroll
        for (int fm = 0; fm < 2; ++fm) {
            float rs0 = 0.f, rs1 = 0.f;
            int row0 = wm*32 + fm*16 + g;
            #pragma unroll
            for (int fn = 0; fn < 4; ++fn) {
                float p0 = ex2f(sacc[fm][fn][0] * LOG2E);
                float p1 = ex2f(sacc[fm][fn][1] * LOG2E);
                float p2 = ex2f(sacc[fm][fn][2] * LOG2E);
                float p3 = ex2f(sacc[fm][fn][3] * LOG2E);
                rs0 += p0 + p1; rs1 += p2 + p3;
                int c = wn*32 + fn*8 + 2*t;
                *(__half2*)&Ps[row0*AQS + c]       = __floats2half2_rn(p0, p1);
                *(__half2*)&Ps[(row0 + 8)*AQS + c] = __floats2half2_rn(p2, p3);
            }
            dreg[fm][0] += rs0;
            dreg[fm][1] += rs1;
        }
        __syncthreads();   // Ps complete (cross-wn exchange for PV)

        // O += P @ V; next iteration's first barrier orders stage reuse
        const uint32_t vbs = vb + st * stageB;
        #pragma unroll
        for (int kk = 0; kk < 4; ++kk) {
            uint32_t afr[2][4];
            #pragma unroll
            for (int fm = 0; fm < 2; ++fm)
                ldm4(afr[fm], pb + (uint32_t)((wm*32 + fm*16 + (lane & 15))*AQS
                                              + kk*16 + (lane >> 4)*8) * 2u);
            #pragma unroll
            for (int nb = 0; nb < 2; ++nb) {
                uint32_t bfr[4];
                ldm4t(bfr, vbs + (uint32_t)((kk*16 + ((lane >> 3) & 1)*8 + (lane & 7))*AQS
                                            + wn*32 + nb*16 + (lane >> 4)*8) * 2u);
                #pragma unroll
                for (int fm = 0; fm < 2; ++fm) {
                    mmah(oacc[fm][2*nb],     afr[fm], bfr[0], bfr[1]);
                    mmah(oacc[fm][2*nb + 1], afr[fm], bfr[2], bfr[3]);
                }
            }
        }
    }

    // final denominator reduce: lanes t -> lane sum via shfl, combine wn halves in smem
    #pragma unroll
    for (int fm = 0; fm < 2; ++fm) {
        float rs0 = dreg[fm][0], rs1 = dreg[fm][1];
        rs0 += __shfl_xor_sync(0xffffffffu, rs0, 1);
        rs0 += __shfl_xor_sync(0xffffffffu, rs0, 2);
        rs1 += __shfl_xor_sync(0xffffffffu, rs1, 1);
        rs1 += __shfl_xor_sync(0xffffffffu, rs1, 2);
        int row0 = wm*32 + fm*16 + g;
        if (t == 0) {
            rsum2[wn*128 + row0]     = rs0;
            rsum2[wn*128 + row0 + 8] = rs1;
        }
    }
    __syncthreads();
    if (tid < 128) g_PD[x*128 + tid] = rsum2[tid] + rsum2[128 + tid];

    #pragma unroll
    for (int fm = 0; fm < 2; ++fm) {
        int row0 = wm*32 + fm*16 + g;
        int row1 = row0 + 8;
        #pragma unroll
        for (int fn = 0; fn < 4; ++fn) {
            int c = wn*32 + fn*8 + 2*t;
            if (row0 < SEQL)
                *(float2*)&g_PO[((long long)x*SEQL + row0)*HD + c] =
                    make_float2(oacc[fm][fn][0], oacc[fm][fn][1]);
            if (row1 < SEQL)
                *(float2*)&g_PO[((long long)x*SEQL + row1)*HD + c] =
                    make_float2(oacc[fm][fn][2], oacc[fm][fn][3]);
        }
    }
}

// ---------------- attention reduce ----------------------------------------------
__global__ void attn_reduce()
{
    const int row = blockIdx.x;
    const int b = row / SEQL, l = row % SEQL;
    const int c = threadIdx.x;             // 0..511
    const int h = c >> 6, d = c & 63;
    const int xb = (b * NHEAD + h) * NSPLIT;
    float num = 0.f, den = 0.f;
    #pragma unroll
    for (int s = 0; s < NSPLIT; ++s) {
        num += g_PO[((long long)(xb + s)*SEQL + l)*HD + d];
        den += g_PD[(xb + s)*128 + l];
    }
    g_AOh[(long long)row * DIM + c] = __float2half_rn(num / den);
}

// ---------------- LayerNorm(a + t) -----------------------------------------------
__global__ void ln_add_k(const float* __restrict__ a, const float* __restrict__ tt,
                         const float* __restrict__ w, const float* __restrict__ bb,
                         float* __restrict__ o, __half* __restrict__ oh)
{
    __shared__ float red[4];
    __shared__ float smu, sinv;
    int row = blockIdx.x, tid = threadIdx.x;   // 128 threads
    const float* pa = a  + (long long)row * DIM;
    const float* pt = tt + (long long)row * DIM;
    float v[4]; float s = 0.f;
    #pragma unroll
    for (int i = 0; i < 4; ++i) {
        v[i] = pa[tid + i*128] + pt[tid + i*128];
        s += v[i];
    }
    #pragma unroll
    for (int off = 16; off; off >>= 1) s += __shfl_xor_sync(0xffffffffu, s, off);
    if ((tid & 31) == 0) red[tid >> 5] = s;
    __syncthreads();
    if (tid == 0) smu = (red[0] + red[1] + red[2] + red[3]) * (1.f / 512.f);
    __syncthreads();
    float mu = smu; float s2 = 0.f;
    #pragma unroll
    for (int i = 0; i < 4; ++i) { float d = v[i] - mu; s2 += d * d; }
    #pragma unroll
    for (int off = 16; off; off >>= 1) s2 += __shfl_xor_sync(0xffffffffu, s2, off);
    if ((tid & 31) == 0) red[tid >> 5] = s2;
    __syncthreads();
    if (tid == 0) sinv = rsqrtf((red[0] + red[1] + red[2] + red[3]) * (1.f / 512.f) + 1e-5f);
    __syncthreads();
    float inv = sinv;
    #pragma unroll
    for (int i = 0; i < 4; ++i) {
        int c = tid + i*128;
        float y = (v[i] - mu) * inv * w[c] + bb[c];
        if (o)  o [(long long)row * DIM + c] = y;
        if (oh) oh[(long long)row * DIM + c] = __float2half_rn(y);
    }
}

// ---------------- launch -----------------------------------------------------------
extern "C" void kernel_launch(void* const* d_in, const int* in_sizes, int n_in,
                              void* d_out, int out_size)
{
    const float* query = (const float*)d_in[0];
    const float* feats = (const float*)d_in[1];
    const float* Wq    = (const float*)d_in[2];
    const float* Wk    = (const float*)d_in[3];
    const float* Wv    = (const float*)d_in[4];
    const float* Wp    = (const float*)d_in[5];
    const float* bp    = (const float*)d_in[6];
    const float* W1    = (const float*)d_in[7];
    const float* b1    = (const float*)d_in[8];
    const float* W2    = (const float*)d_in[9];
    const float* b2    = (const float*)d_in[10];
    const float* ln0w  = (const float*)d_in[11];
    const float* ln0b  = (const float*)d_in[12];
    const float* ln2w  = (const float*)d_in[13];
    const float* ln2b  = (const float*)d_in[14];
    float* out = (float*)d_out;

    __half *pFh, *pK2, *pV2, *pQryh, *pWqh, *pWkh, *pWvh, *pWph, *pW1h, *pW2h;
    __half *pQh, *pAOh, *pXh, *pHh;
    float *pX, *pT;
    cudaGetSymbolAddress((void**)&pFh,   g_featsh);
    cudaGetSymbolAddress((void**)&pK2,   g_K2);
    cudaGetSymbolAddress((void**)&pV2,   g_V2);
    cudaGetSymbolAddress((void**)&pQryh, g_queryh);
    cudaGetSymbolAddress((void**)&pWqh,  g_Wqh);
    cudaGetSymbolAddress((void**)&pWkh,  g_Wkh);
    cudaGetSymbolAddress((void**)&pWvh,  g_Wvh);
    cudaGetSymbolAddress((void**)&pWph,  g_Wph);
    cudaGetSymbolAddress((void**)&pW1h,  g_W1h);
    cudaGetSymbolAddress((void**)&pW2h,  g_W2h);
    cudaGetSymbolAddress((void**)&pQh,   g_Qh);
    cudaGetSymbolAddress((void**)&pAOh,  g_AOh);
    cudaGetSymbolAddress((void**)&pXh,   g_Xh);
    cudaGetSymbolAddress((void**)&pHh,   g_Hh);
    cudaGetSymbolAddress((void**)&pX,    g_X);
    cudaGetSymbolAddress((void**)&pT,    g_T);

    cudaFuncSetAttribute(gemm_hh, cudaFuncAttributeMaxDynamicSharedMemorySize, GH_SMEM);
    cudaFuncSetAttribute(attn_k,  cudaFuncAttributeMaxDynamicSharedMemorySize, ATTN_SMEM);

    // 0. feats -> half
    cvt_h<<<8192, 256>>>(feats, pFh, (long long)NBATCH*HW*DIM);
    // 1. Wq,Wk,Wv -> half
    cvt_h3<<<dim3(64, 3), 256>>>(Wq, Wk, Wv, pWqh, pWkh, pWvh, DIM*DIM);
    // 2. fused K,V projections -> g_K2, g_V2 (half)
    gemm_hh<<<dim3(8, 2048, 1), 256, GH_SMEM>>>(pFh, pWkh, pWvh, pK2, pV2,
                                                NBATCH*HW, DIM, 4, 1, 1.f, nullptr, 0,
                                                0, 0, 0);
    // 3. query -> half
    cvt_h<<<400, 256>>>(query, pQryh, (long long)MROWS*DIM);
    // 4. Wp,W1,W2 -> half
    cvt_h3<<<dim3(64, 3), 256>>>(Wp, W1, W2, pWph, pW1h, pW2h, DIM*DIM);
    // 5. q = 0.125 * query @ Wq^T -> g_Qh
    gemm_hh<<<dim3(4, 13, 1), 256, GH_SMEM>>>(pQryh, pWqh, pWqh, pQh, pQh,
                                              MROWS, DIM, 999, 1, 0.125f, nullptr, 0,
                                              0, 0, 0);
    // 6-7. attention partials + reduce -> g_AOh
    attn_k<<<NBATCH * NHEAD * NSPLIT, 256, ATTN_SMEM>>>();
    attn_reduce<<<MROWS, 512>>>();
    // 8. mask = q @ K^T per batch -> d_out tail (f32)
    gemm_hh<<<dim3(HW/128, 1, NBATCH), 256, GH_SMEM>>>(pQh, pK2, pK2,
                                              out + (long long)MROWS*DIM,
                                              out + (long long)MROWS*DIM,
                                              SEQL, HW, 999, 0, 1.f, nullptr, 0,
                                              (long long)SEQL*DIM,
                                              (long long)HW*DIM,
                                              (long long)SEQL*HW);
    // 9. attn_out @ Wp^T + bp -> g_T (f32)
    gemm_hh<<<dim3(4, 13, 1), 256, GH_SMEM>>>(pAOh, pWph, pWph, pT, pT,
                                              MROWS, DIM, 999, 0, 1.f, bp, 0, 0, 0, 0);
    // 10. x = LN(query + t)
    ln_add_k<<<MROWS, 128>>>(query, pT, ln0w, ln0b, pX, pXh);
    // 11. h = relu(x @ W1^T + b1) -> g_Hh
    gemm_hh<<<dim3(4, 13, 1), 256, GH_SMEM>>>(pXh, pW1h, pW1h, pHh, pHh,
                                              MROWS, DIM, 999, 1, 1.f, b1, 1, 0, 0, 0);
    // 12. f = h @ W2^T + b2 -> g_T
    gemm_hh<<<dim3(4, 13, 1), 256, GH_SMEM>>>(pHh, pW2h, pW2h, pT, pT,
                                              MROWS, DIM, 999, 0, 1.f, b2, 0, 0, 0, 0);
    // 13. y = LN(x + f) -> d_out head
    ln_add_k<<<MROWS, 128>>>(pX, pT, ln2w, ln2b, out, nullptr);
}

// round 17
// speedup vs baseline: 1.0370x; 1.0000x over previous
#include <cuda_runtime.h>
#include <cuda_fp16.h>
#include <stdint.h>

#define NBATCH 16
#define SEQL   100
#define DIM    512
#define HW     16384
#define NHEAD  8
#define HD     64
#define MROWS  (NBATCH*SEQL)
#define LOG2E  1.4426950408889634f
#define NSPLIT 8
#define SPLEN  (HW / NSPLIT)

// ---------------- scratch (device globals; no allocation allowed) -------------
__device__ __half g_featsh[(size_t)NBATCH*HW*DIM];   // 256 MB
__device__ __half g_K2[(size_t)NBATCH*HW*DIM];       // 256 MB
__device__ __half g_V2[(size_t)NBATCH*HW*DIM];       // 256 MB
__device__ __half g_queryh[MROWS*DIM];
__device__ __half g_Wqh[DIM*DIM];
__device__ __half g_Wkh[DIM*DIM];
__device__ __half g_Wvh[DIM*DIM];
__device__ __half g_Wph[DIM*DIM];
__device__ __half g_W1h[DIM*DIM];
__device__ __half g_W2h[DIM*DIM];
__device__ __half g_Qh [MROWS*DIM];
__device__ __half g_AOh[MROWS*DIM];
__device__ __half g_Xh [MROWS*DIM];
__device__ __half g_Hh [MROWS*DIM];
__device__ float  g_X  [MROWS*DIM];
__device__ float  g_T  [MROWS*DIM];
__device__ float  g_PO[(size_t)NBATCH*NHEAD*NSPLIT*SEQL*HD];
__device__ float  g_PD[NBATCH*NHEAD*NSPLIT*128];

// ---------------- helpers ------------------------------------------------------
__device__ __forceinline__ uint32_t smem_u32(const void* p) {
    uint32_t a;
    asm("{ .reg .u64 t; cvta.to.shared.u64 t, %1; cvt.u32.u64 %0, t; }" : "=r"(a) : "l"(p));
    return a;
}
__device__ __forceinline__ void ldm4(uint32_t* r, uint32_t addr) {
    asm volatile("ldmatrix.sync.aligned.m8n8.x4.shared.b16 {%0,%1,%2,%3}, [%4];"
                 : "=r"(r[0]), "=r"(r[1]), "=r"(r[2]), "=r"(r[3]) : "r"(addr));
}
__device__ __forceinline__ void ldm4t(uint32_t* r, uint32_t addr) {
    asm volatile("ldmatrix.sync.aligned.m8n8.x4.trans.shared.b16 {%0,%1,%2,%3}, [%4];"
                 : "=r"(r[0]), "=r"(r[1]), "=r"(r[2]), "=r"(r[3]) : "r"(addr));
}
__device__ __forceinline__ void mmah(float* c, const uint32_t* a, uint32_t b0, uint32_t b1) {
    asm volatile("mma.sync.aligned.m16n8k16.row.col.f32.f16.f16.f32 "
                 "{%0,%1,%2,%3},{%4,%5,%6,%7},{%8,%9},{%0,%1,%2,%3};"
                 : "+f"(c[0]), "+f"(c[1]), "+f"(c[2]), "+f"(c[3])
                 : "r"(a[0]), "r"(a[1]), "r"(a[2]), "r"(a[3]), "r"(b0), "r"(b1));
}
__device__ __forceinline__ float ex2f(float x) {
    float y; asm("ex2.approx.f32 %0, %1;" : "=f"(y) : "f"(x)); return y;
}
// .ca (measured best: .cg regressed in R15)
__device__ __forceinline__ void cpa16(uint32_t dst, const void* src) {
    asm volatile("cp.async.ca.shared.global [%0], [%1], 16;" :: "r"(dst), "l"(src));
}
#define CPCOMMIT() asm volatile("cp.async.commit_group;")
#define CPWAIT1()  asm volatile("cp.async.wait_group 1;")
#define CPWAIT0()  asm volatile("cp.async.wait_group 0;")

// ---------------- f32 -> f16 conversions ----------------------------------------
__global__ void cvt_h(const float* __restrict__ src, __half* __restrict__ dst, long long n)
{
    long long stride = (long long)gridDim.x * blockDim.x * 8;
    for (long long i = ((long long)blockIdx.x * blockDim.x + threadIdx.x) * 8;
         i < n; i += stride) {
        float4 a = *(const float4*)(src + i);
        float4 b = *(const float4*)(src + i + 4);
        __half2 h[4] = { __floats2half2_rn(a.x, a.y), __floats2half2_rn(a.z, a.w),
                         __floats2half2_rn(b.x, b.y), __floats2half2_rn(b.z, b.w) };
        *(uint4*)(dst + i) = *(uint4*)h;
    }
}

// one launch converting 6 weight matrices + query (blockIdx.y selects tensor)
__global__ void cvt_all(const float* __restrict__ s0, const float* __restrict__ s1,
                        const float* __restrict__ s2, const float* __restrict__ s3,
                        const float* __restrict__ s4, const float* __restrict__ s5,
                        const float* __restrict__ s6,
                        __half* __restrict__ d0, __half* __restrict__ d1,
                        __half* __restrict__ d2, __half* __restrict__ d3,
                        __half* __restrict__ d4, __half* __restrict__ d5,
                        __half* __restrict__ d6)
{
    const float* srcs[7] = { s0, s1, s2, s3, s4, s5, s6 };
    __half*      dsts[7] = { d0, d1, d2, d3, d4, d5, d6 };
    const int y = blockIdx.y;
    const float* s = srcs[y];
    __half*      d = dsts[y];
    const long long n = (y == 6) ? (long long)MROWS * DIM : (long long)DIM * DIM;
    long long stride = (long long)gridDim.x * blockDim.x * 8;
    for (long long i = ((long long)blockIdx.x * blockDim.x + threadIdx.x) * 8;
         i < n; i += stride) {
        float4 a = *(const float4*)(s + i);
        float4 b = *(const float4*)(s + i + 4);
        __half2 h[4] = { __floats2half2_rn(a.x, a.y), __floats2half2_rn(a.z, a.w),
                         __floats2half2_rn(b.x, b.y), __floats2half2_rn(b.z, b.w) };
        *(uint4*)(d + i) = *(uint4*)h;
    }
}

// ---------------- half GEMM: BM=128, BN=128, BK=32, 3-stage cp.async ------------
// 256 threads, 8 warps in 4x2 grid of 32x64 tiles, occupancy 2. (champion config)
#define GS2 40
#define GH_SMEM (3 * 2 * 128 * GS2 * 2)   // 61440 bytes

__global__ __launch_bounds__(256, 2)
void gemm_hh(const __half* __restrict__ A,
             const __half* __restrict__ B0, const __half* __restrict__ B1,
             void* __restrict__ C0v, void* __restrict__ C1v,
             int M, int ldc, int nsplitBlk, int outhalf,
             float alpha, const float* __restrict__ bias, int relu,
             long long sAz, long long sBz, long long sCz)
{
    extern __shared__ char smraw[];
    const uint32_t sa = smem_u32(smraw);
    const uint32_t sb = sa + 3u * 128 * GS2 * 2u;
    const int tid = threadIdx.x, lane = tid & 31, warp = tid >> 5;
    const int wm = warp >> 1, wn = warp & 1;
    const int g = lane >> 2, t = lane & 3;
    const int bm = blockIdx.y * 128;
    const int bx = blockIdx.x;
    const long long z = blockIdx.z;

    const __half* Bp; int bc;
    if (bx >= nsplitBlk) { Bp = B1; bc = (bx - nsplitBlk) * 128; }
    else                 { Bp = B0; bc = bx * 128; }

    const int r0l = tid >> 2;
    const int c8  = (tid & 3) * 8;
    int ar0 = bm + r0l;       if (ar0 > M - 1) ar0 = M - 1;
    int ar1 = bm + r0l + 64;  if (ar1 > M - 1) ar1 = M - 1;
    const __half* Ag0 = A  + z * sAz + (long long)ar0 * 512 + c8;
    const __half* Ag1 = A  + z * sAz + (long long)ar1 * 512 + c8;
    const __half* Bg0 = Bp + z * sBz + (long long)(bc + r0l) * 512 + c8;
    const __half* Bg1 = Bp + z * sBz + (long long)(bc + r0l + 64) * 512 + c8;
    const uint32_t da0 = sa + (uint32_t)(r0l * GS2 + c8) * 2u;
    const uint32_t da1 = sa + (uint32_t)((r0l + 64) * GS2 + c8) * 2u;
    const uint32_t db0 = sb + (uint32_t)(r0l * GS2 + c8) * 2u;
    const uint32_t db1 = sb + (uint32_t)((r0l + 64) * GS2 + c8) * 2u;
    const uint32_t bufb = 128 * GS2 * 2u;

    #define GLOAD(kt, st) do {                                   \
        uint32_t o = (uint32_t)(st) * bufb;                      \
        cpa16(da0 + o, Ag0 + (kt)*32);                           \
        cpa16(da1 + o, Ag1 + (kt)*32);                           \
        cpa16(db0 + o, Bg0 + (kt)*32);                           \
        cpa16(db1 + o, Bg1 + (kt)*32);                           \
        CPCOMMIT();                                              \
    } while (0)

    float acc[2][8][4];
    #pragma unroll
    for (int i = 0; i < 2; ++i)
        #pragma unroll
        for (int j = 0; j < 8; ++j)
            #pragma unroll
            for (int k = 0; k < 4; ++k) acc[i][j][k] = 0.f;

    GLOAD(0, 0);
    GLOAD(1, 1);

    #pragma unroll 1
    for (int kt = 0; kt < 16; ++kt) {
        if (kt < 15) CPWAIT1(); else CPWAIT0();
        __syncthreads();
        if (kt < 14) {
            int st = (kt + 2) % 3;
            GLOAD(kt + 2, st);
        }
        int sc = kt % 3;
        const uint32_t ab = sa + sc * bufb;
        const uint32_t bb = sb + sc * bufb;
        #pragma unroll
        for (int kk = 0; kk < 2; ++kk) {
            uint32_t afr[2][4];
            #pragma unroll
            for (int fm = 0; fm < 2; ++fm)
                ldm4(afr[fm], ab + (uint32_t)((wm*32 + fm*16 + (lane & 15))*GS2
                                              + kk*16 + (lane >> 4)*8) * 2u);
            #pragma unroll
            for (int nb = 0; nb < 4; ++nb) {
                uint32_t bfr[4];
                ldm4(bfr, bb + (uint32_t)((wn*64 + nb*16 + (lane >> 4)*8 + (lane & 7))*GS2
                                          + kk*16 + ((lane >> 3) & 1)*8) * 2u);
                #pragma unroll
                for (int fm = 0; fm < 2; ++fm) {
                    mmah(acc[fm][2*nb],     afr[fm], bfr[0], bfr[1]);
                    mmah(acc[fm][2*nb + 1], afr[fm], bfr[2], bfr[3]);
                }
            }
        }
    }

    float*  Cf = (bx >= nsplitBlk) ? (float*)C1v  : (float*)C0v;
    __half* Ch = (bx >= nsplitBlk) ? (__half*)C1v : (__half*)C0v;
    Cf += z * sCz; Ch += z * sCz;
    #pragma unroll
    for (int fm = 0; fm < 2; ++fm) {
        int r0 = bm + wm*32 + fm*16 + g;
        int r1 = r0 + 8;
        #pragma unroll
        for (int fn = 0; fn < 8; ++fn) {
            int c = bc + wn*64 + fn*8 + 2*t;
            float b0v = 0.f, b1v = 0.f;
            if (bias) { b0v = bias[c]; b1v = bias[c + 1]; }
            float v0 = acc[fm][fn][0]*alpha + b0v;
            float v1 = acc[fm][fn][1]*alpha + b1v;
            float v2 = acc[fm][fn][2]*alpha + b0v;
            float v3 = acc[fm][fn][3]*alpha + b1v;
            if (relu) {
                v0 = fmaxf(v0, 0.f); v1 = fmaxf(v1, 0.f);
                v2 = fmaxf(v2, 0.f); v3 = fmaxf(v3, 0.f);
            }
            if (outhalf) {
                if (r0 < M) *(__half2*)&Ch[(long long)r0*ldc + c] = __floats2half2_rn(v0, v1);
                if (r1 < M) *(__half2*)&Ch[(long long)r1*ldc + c] = __floats2half2_rn(v2, v3);
            } else {
                if (r0 < M) *(float2*)&Cf[(long long)r0*ldc + c] = make_float2(v0, v1);
                if (r1 < M) *(float2*)&Cf[(long long)r1*ldc + c] = make_float2(v2, v3);
            }
        }
    }
}

// ---------------- attention: fp16 flash, split-K x8, 3-stage cp.async K/V -------
#define AQS 72
#define NCH (SPLEN / 64)    // 32 chunks per split
#define ATTN_SMEM ((128 + 3*64 + 3*64 + 128) * AQS * 2 + 256 * 4)

__global__ __launch_bounds__(256, 2)
void attn_k()
{
    extern __shared__ char smraw[];
    __half* Qs = (__half*)smraw;          // 128*AQS
    __half* Ks = Qs + 128*AQS;            // 3 stages x 64*AQS
    __half* Vs = Ks + 3*64*AQS;           // 3 stages x 64*AQS
    __half* Ps = Vs + 3*64*AQS;           // 128*AQS
    float* rsum2 = (float*)(Ps + 128*AQS);   // 256 (two wn banks, used once at end)

    const int x = blockIdx.x;
    const int split = x & (NSPLIT - 1), bh = x >> 3;
    const int b = bh >> 3, h = bh & 7;
    const int tid = threadIdx.x, lane = tid & 31, warp = tid >> 5;
    const int g = lane >> 2, t = lane & 3;
    const int wm = warp >> 1, wn = warp & 1;
    const int k0 = split * SPLEN;

    const uint32_t qb = smem_u32(Qs), kb = smem_u32(Ks);
    const uint32_t vb = smem_u32(Vs), pb = smem_u32(Ps);
    const uint32_t stageB = 64 * AQS * 2u;

    const int rr = tid >> 2, cc = (tid & 3) * 16;
    const uint32_t dk = kb + (uint32_t)(rr * AQS + cc) * 2u;
    const uint32_t dv = vb + (uint32_t)(rr * AQS + cc) * 2u;

    #define ALOAD(ci, st) do {                                                  \
        long long off = ((long long)(b*HW + k0 + (ci)*64 + rr))*DIM + h*HD + cc;\
        uint32_t o = (uint32_t)(st) * stageB;                                   \
        cpa16(dk + o,      g_K2 + off);                                         \
        cpa16(dk + o + 16, g_K2 + off + 8);                                     \
        cpa16(dv + o,      g_V2 + off);                                         \
        cpa16(dv + o + 16, g_V2 + off + 8);                                     \
        CPCOMMIT();                                                             \
    } while (0)

    // Q tile [128 x 64] half; zero rows >= 100
    {
        int r = tid >> 1, c0 = (tid & 1) * 32;
        const __half* src = g_Qh + (long long)(b*SEQL + (r < SEQL ? r : 0))*DIM + h*HD + c0;
        uint4 z4 = make_uint4(0, 0, 0, 0);
        #pragma unroll
        for (int j = 0; j < 4; ++j) {
            uint4 v = (r < SEQL) ? ((const uint4*)src)[j] : z4;
            *(uint4*)&Qs[r*AQS + c0 + j*8] = v;
        }
    }

    float oacc[2][4][4];
    #pragma unroll
    for (int i = 0; i < 2; ++i)
        #pragma unroll
        for (int j = 0; j < 4; ++j)
            #pragma unroll
            for (int k = 0; k < 4; ++k) oacc[i][j][k] = 0.f;

    // running denominators (this warp's wn key-half) for rows fm*16+g, +8
    float dreg[2][2] = {{0.f, 0.f}, {0.f, 0.f}};

    ALOAD(0, 0);
    ALOAD(1, 1);

    #pragma unroll 1
    for (int ci = 0; ci < NCH; ++ci) {
        const int st = ci % 3;
        if (ci < NCH - 1) CPWAIT1(); else CPWAIT0();
        __syncthreads();   // chunk ci visible; prior iter's PV done CTA-wide
        if (ci + 2 < NCH) ALOAD(ci + 2, (ci + 2) % 3);

        // S = Q @ K^T  (warp: 32 q-rows x 32 keys)
        const uint32_t kbs = kb + st * stageB;
        float sacc[2][4][4];
        #pragma unroll
        for (int i = 0; i < 2; ++i)
            #pragma unroll
            for (int j = 0; j < 4; ++j)
                #pragma unroll
                for (int k = 0; k < 4; ++k) sacc[i][j][k] = 0.f;
        #pragma unroll
        for (int ks = 0; ks < 4; ++ks) {
            uint32_t afr[2][4];
            #pragma unroll
            for (int fm = 0; fm < 2; ++fm)
                ldm4(afr[fm], qb + (uint32_t)((wm*32 + fm*16 + (lane & 15))*AQS
                                              + ks*16 + (lane >> 4)*8) * 2u);
            #pragma unroll
            for (int nb = 0; nb < 2; ++nb) {
                uint32_t bfr[4];
                ldm4(bfr, kbs + (uint32_t)((wn*32 + nb*16 + (lane >> 4)*8 + (lane & 7))*AQS
                                           + ks*16 + ((lane >> 3) & 1)*8) * 2u);
                #pragma unroll
                for (int fm = 0; fm < 2; ++fm) {
                    mmah(sacc[fm][2*nb],     afr[fm], bfr[0], bfr[1]);
                    mmah(sacc[fm][2*nb + 1], afr[fm], bfr[2], bfr[3]);
                }
            }
        }

        // P = exp(S) -> Ps; accumulate row sums in registers
        #pragma unroll
        for (int fm = 0; fm < 2; ++fm) {
            float rs0 = 0.f, rs1 = 0.f;
            int row0 = wm*32 + fm*16 + g;
            #pragma unroll
            for (int fn = 0; fn < 4; ++fn) {
                float p0 = ex2f(sacc[fm][fn][0] * LOG2E);
                float p1 = ex2f(sacc[fm][fn][1] * LOG2E);
                float p2 = ex2f(sacc[fm][fn][2] * LOG2E);
                float p3 = ex2f(sacc[fm][fn][3] * LOG2E);
                rs0 += p0 + p1; rs1 += p2 + p3;
                int c = wn*32 + fn*8 + 2*t;
                *(__half2*)&Ps[row0*AQS + c]       = __floats2half2_rn(p0, p1);
                *(__half2*)&Ps[(row0 + 8)*AQS + c] = __floats2half2_rn(p2, p3);
            }
            dreg[fm][0] += rs0;
            dreg[fm][1] += rs1;
        }
        __syncthreads();   // Ps complete (cross-wn exchange for PV)

        // O += P @ V; next iteration's first barrier orders stage reuse
        const uint32_t vbs = vb + st * stageB;
        #pragma unroll
        for (int kk = 0; kk < 4; ++kk) {
            uint32_t afr[2][4];
            #pragma unroll
            for (int fm = 0; fm < 2; ++fm)
                ldm4(afr[fm], pb + (uint32_t)((wm*32 + fm*16 + (lane & 15))*AQS
                                              + kk*16 + (lane >> 4)*8) * 2u);
            #pragma unroll
            for (int nb = 0; nb < 2; ++nb) {
                uint32_t bfr[4];
                ldm4t(bfr, vbs + (uint32_t)((kk*16 + ((lane >> 3) & 1)*8 + (lane & 7))*AQS
                                            + wn*32 + nb*16 + (lane >> 4)*8) * 2u);
                #pragma unroll
                for (int fm = 0; fm < 2; ++fm) {
                    mmah(oacc[fm][2*nb],     afr[fm], bfr[0], bfr[1]);
                    mmah(oacc[fm][2*nb + 1], afr[fm], bfr[2], bfr[3]);
                }
            }
        }
    }

    // final denominator reduce: lane groups via shfl, combine wn halves in smem once
    #pragma unroll
    for (int fm = 0; fm < 2; ++fm) {
        float rs0 = dreg[fm][0], rs1 = dreg[fm][1];
        rs0 += __shfl_xor_sync(0xffffffffu, rs0, 1);
        rs0 += __shfl_xor_sync(0xffffffffu, rs0, 2);
        rs1 += __shfl_xor_sync(0xffffffffu, rs1, 1);
        rs1 += __shfl_xor_sync(0xffffffffu, rs1, 2);
        int row0 = wm*32 + fm*16 + g;
        if (t == 0) {
            rsum2[wn*128 + row0]     = rs0;
            rsum2[wn*128 + row0 + 8] = rs1;
        }
    }
    __syncthreads();
    if (tid < 128) g_PD[x*128 + tid] = rsum2[tid] + rsum2[128 + tid];

    #pragma unroll
    for (int fm = 0; fm < 2; ++fm) {
        int row0 = wm*32 + fm*16 + g;
        int row1 = row0 + 8;
        #pragma unroll
        for (int fn = 0; fn < 4; ++fn) {
            int c = wn*32 + fn*8 + 2*t;
            if (row0 < SEQL)
                *(float2*)&g_PO[((long long)x*SEQL + row0)*HD + c] =
                    make_float2(oacc[fm][fn][0], oacc[fm][fn][1]);
            if (row1 < SEQL)
                *(float2*)&g_PO[((long long)x*SEQL + row1)*HD + c] =
                    make_float2(oacc[fm][fn][2], oacc[fm][fn][3]);
        }
    }
}

// ---------------- attention reduce ----------------------------------------------
__global__ void attn_reduce()
{
    const int row = blockIdx.x;
    const int b = row / SEQL, l = row % SEQL;
    const int c = threadIdx.x;             // 0..511
    const int h = c >> 6, d = c & 63;
    const int xb = (b * NHEAD + h) * NSPLIT;
    float num = 0.f, den = 0.f;
    #pragma unroll
    for (int s = 0; s < NSPLIT; ++s) {
        num += g_PO[((long long)(xb + s)*SEQL + l)*HD + d];
        den += g_PD[(xb + s)*128 + l];
    }
    g_AOh[(long long)row * DIM + c] = __float2half_rn(num / den);
}

// ---------------- LayerNorm(a + t) -----------------------------------------------
__global__ void ln_add_k(const float* __restrict__ a, const float* __restrict__ tt,
                         const float* __restrict__ w, const float* __restrict__ bb,
                         float* __restrict__ o, __half* __restrict__ oh)
{
    __shared__ float red[4];
    __shared__ float smu, sinv;
    int row = blockIdx.x, tid = threadIdx.x;   // 128 threads
    const float* pa = a  + (long long)row * DIM;
    const float* pt = tt + (long long)row * DIM;
    float v[4]; float s = 0.f;
    #pragma unroll
    for (int i = 0; i < 4; ++i) {
        v[i] = pa[tid + i*128] + pt[tid + i*128];
        s += v[i];
    }
    #pragma unroll
    for (int off = 16; off; off >>= 1) s += __shfl_xor_sync(0xffffffffu, s, off);
    if ((tid & 31) == 0) red[tid >> 5] = s;
    __syncthreads();
    if (tid == 0) smu = (red[0] + red[1] + red[2] + red[3]) * (1.f / 512.f);
    __syncthreads();
    float mu = smu; float s2 = 0.f;
    #pragma unroll
    for (int i = 0; i < 4; ++i) { float d = v[i] - mu; s2 += d * d; }
    #pragma unroll
    for (int off = 16; off; off >>= 1) s2 += __shfl_xor_sync(0xffffffffu, s2, off);
    if ((tid & 31) == 0) red[tid >> 5] = s2;
    __syncthreads();
    if (tid == 0) sinv = rsqrtf((red[0] + red[1] + red[2] + red[3]) * (1.f / 512.f) + 1e-5f);
    __syncthreads();
    float inv = sinv;
    #pragma unroll
    for (int i = 0; i < 4; ++i) {
        int c = tid + i*128;
        float y = (v[i] - mu) * inv * w[c] + bb[c];
        if (o)  o [(long long)row * DIM + c] = y;
        if (oh) oh[(long long)row * DIM + c] = __float2half_rn(y);
    }
}

// ---------------- launch -----------------------------------------------------------
extern "C" void kernel_launch(void* const* d_in, const int* in_sizes, int n_in,
                              void* d_out, int out_size)
{
    const float* query = (const float*)d_in[0];
    const float* feats = (const float*)d_in[1];
    const float* Wq    = (const float*)d_in[2];
    const float* Wk    = (const float*)d_in[3];
    const float* Wv    = (const float*)d_in[4];
    const float* Wp    = (const float*)d_in[5];
    const float* bp    = (const float*)d_in[6];
    const float* W1    = (const float*)d_in[7];
    const float* b1    = (const float*)d_in[8];
    const float* W2    = (const float*)d_in[9];
    const float* b2    = (const float*)d_in[10];
    const float* ln0w  = (const float*)d_in[11];
    const float* ln0b  = (const float*)d_in[12];
    const float* ln2w  = (const float*)d_in[13];
    const float* ln2b  = (const float*)d_in[14];
    float* out = (float*)d_out;

    __half *pFh, *pK2, *pV2, *pQryh, *pWqh, *pWkh, *pWvh, *pWph, *pW1h, *pW2h;
    __half *pQh, *pAOh, *pXh, *pHh;
    float *pX, *pT;
    cudaGetSymbolAddress((void**)&pFh,   g_featsh);
    cudaGetSymbolAddress((void**)&pK2,   g_K2);
    cudaGetSymbolAddress((void**)&pV2,   g_V2);
    cudaGetSymbolAddress((void**)&pQryh, g_queryh);
    cudaGetSymbolAddress((void**)&pWqh,  g_Wqh);
    cudaGetSymbolAddress((void**)&pWkh,  g_Wkh);
    cudaGetSymbolAddress((void**)&pWvh,  g_Wvh);
    cudaGetSymbolAddress((void**)&pWph,  g_Wph);
    cudaGetSymbolAddress((void**)&pW1h,  g_W1h);
    cudaGetSymbolAddress((void**)&pW2h,  g_W2h);
    cudaGetSymbolAddress((void**)&pQh,   g_Qh);
    cudaGetSymbolAddress((void**)&pAOh,  g_AOh);
    cudaGetSymbolAddress((void**)&pXh,   g_Xh);
    cudaGetSymbolAddress((void**)&pHh,   g_Hh);
    cudaGetSymbolAddress((void**)&pX,    g_X);
    cudaGetSymbolAddress((void**)&pT,    g_T);

    cudaFuncSetAttribute(gemm_hh, cudaFuncAttributeMaxDynamicSharedMemorySize, GH_SMEM);
    cudaFuncSetAttribute(attn_k,  cudaFuncAttributeMaxDynamicSharedMemorySize, ATTN_SMEM);

    // 0. feats -> half
    cvt_h<<<8192, 256>>>(feats, pFh, (long long)NBATCH*HW*DIM);
    // 1. all weights + query -> half (single launch)
    cvt_all<<<dim3(64, 7), 256>>>(Wq, Wk, Wv, Wp, W1, W2, query,
                                  pWqh, pWkh, pWvh, pWph, pW1h, pW2h, pQryh);
    // 2. fused K,V projections -> g_K2, g_V2 (half)
    gemm_hh<<<dim3(8, 2048, 1), 256, GH_SMEM>>>(pFh, pWkh, pWvh, pK2, pV2,
                                                NBATCH*HW, DIM, 4, 1, 1.f, nullptr, 0,
                                                0, 0, 0);
    // 3. q = 0.125 * query @ Wq^T -> g_Qh
    gemm_hh<<<dim3(4, 13, 1), 256, GH_SMEM>>>(pQryh, pWqh, pWqh, pQh, pQh,
                                              MROWS, DIM, 999, 1, 0.125f, nullptr, 0,
                                              0, 0, 0);
    // 4-5. attention partials + reduce -> g_AOh
    attn_k<<<NBATCH * NHEAD * NSPLIT, 256, ATTN_SMEM>>>();
    attn_reduce<<<MROWS, 512>>>();
    // 6. mask = q @ K^T per batch -> d_out tail (f32)
    gemm_hh<<<dim3(HW/128, 1, NBATCH), 256, GH_SMEM>>>(pQh, pK2, pK2,
                                              out + (long long)MROWS*DIM,
                                              out + (long long)MROWS*DIM,
                                              SEQL, HW, 999, 0, 1.f, nullptr, 0,
                                              (long long)SEQL*DIM,
                                              (long long)HW*DIM,
                                              (long long)SEQL*HW);
    // 7. attn_out @ Wp^T + bp -> g_T (f32)
    gemm_hh<<<dim3(4, 13, 1), 256, GH_SMEM>>>(pAOh, pWph, pWph, pT, pT,
                                              MROWS, DIM, 999, 0, 1.f, bp, 0, 0, 0, 0);
    // 8. x = LN(query + t)
    ln_add_k<<<MROWS, 128>>>(query, pT, ln0w, ln0b, pX, pXh);
    // 9. h = relu(x @ W1^T + b1) -> g_Hh
    gemm_hh<<<dim3(4, 13, 1), 256, GH_SMEM>>>(pXh, pW1h, pW1h, pHh, pHh,
                                              MROWS, DIM, 999, 1, 1.f, b1, 1, 0, 0, 0);
    // 10. f = h @ W2^T + b2 -> g_T
    gemm_hh<<<dim3(4, 13, 1), 256, GH_SMEM>>>(pHh, pW2h, pW2h, pT, pT,
                                              MROWS, DIM, 999, 0, 1.f, b2, 0, 0, 0, 0);
    // 11. y = LN(x + f) -> d_out head
    ln_add_k<<<MROWS, 128>>>(pX, pT, ln2w, ln2b, out, nullptr);
}